// round 3
// baseline (speedup 1.0000x reference)
#include <cuda_runtime.h>

#define N_NODES 100000
#define N_EDGES 1638400
#define IN_F    128
#define OUT_F   64
#define N_RELS  8
#define NCOL    (N_RELS * OUT_F)   /* 512 */

// Scratch: XW[n][r*64+o] = sum_f feat[n][f] * W[r][o][f]   (204.8 MB)
__device__ float g_xw[(size_t)N_NODES * NCOL];

// ---------------------------------------------------------------------------
// helpers: packed f32x2 FMA (FFMA2) — 2x fp32 FMA throughput on sm_103a
// ---------------------------------------------------------------------------
__device__ __forceinline__ unsigned long long pk2(float x) {
    unsigned long long r;
    asm("mov.b64 %0, {%1, %1};" : "=l"(r) : "f"(x));
    return r;
}
#define FMA2(d, a, b, c) \
    asm("fma.rn.f32x2 %0, %1, %2, %3;" : "=l"(d) : "l"(a), "l"(b), "l"(c))

// ---------------------------------------------------------------------------
// GEMM: C[m][n] = sum_k A[m][k] * B[n][k],  A=[100000,128], B=[512,128]
// BM=BN=BK=128 tile, 256 threads, 8x8 micro-tile per thread, FFMA2 pairs on n.
// ---------------------------------------------------------------------------
constexpr int BM = 128, BN = 128, BK = 128;
constexpr int LDS_PAD = 4;
constexpr int LDA = BK + LDS_PAD;   // As row length (floats), As[m][k]
constexpr int LDB = BN + LDS_PAD;   // Bs row length (floats), Bs[k][n]
constexpr int SMEM_BYTES = (BM * LDA + BK * LDB) * 4;  // 135168 B

__global__ __launch_bounds__(256)
void gemm_kernel(const float* __restrict__ A, const float* __restrict__ B) {
    extern __shared__ float sm[];
    float* As = sm;              // [BM][LDA]
    float* Bs = sm + BM * LDA;   // [BK][LDB]

    const int t  = threadIdx.x;
    const int bm = blockIdx.x * BM;
    const int bn = blockIdx.y * BN;

    // Load A tile [BM][BK] row-major (guard rows past N_NODES)
#pragma unroll
    for (int it = 0; it < 16; it++) {
        int row = it * 8 + (t >> 5);
        int c4  = (t & 31) * 4;
        int gm  = bm + row;
        float4 v = make_float4(0.f, 0.f, 0.f, 0.f);
        if (gm < N_NODES) v = *(const float4*)(A + (size_t)gm * IN_F + c4);
        *(float4*)(As + row * LDA + c4) = v;
    }
    // Load B tile transposed: Bs[k][n] = B[bn+n][k]  (bn+n < 512 always)
#pragma unroll
    for (int it = 0; it < 16; it++) {
        int n  = it * 8 + (t >> 5);
        int c4 = (t & 31) * 4;
        float4 v = *(const float4*)(B + (size_t)(bn + n) * IN_F + c4);
        Bs[(c4 + 0) * LDB + n] = v.x;
        Bs[(c4 + 1) * LDB + n] = v.y;
        Bs[(c4 + 2) * LDB + n] = v.z;
        Bs[(c4 + 3) * LDB + n] = v.w;
    }
    __syncthreads();

    const int tx = t & 15;       // n-tile position (16 x 8 cols)
    const int ty = t >> 4;       // m-tile position (16 x 8 rows)
    const float* ap = As + (ty * 8) * LDA;
    const float* bp = Bs + tx * 8;

    unsigned long long acc[8][4];
#pragma unroll
    for (int i = 0; i < 8; i++)
#pragma unroll
        for (int j = 0; j < 4; j++) acc[i][j] = 0ull;

#pragma unroll 4
    for (int k = 0; k < BK; k++) {
        ulonglong2 b01 = *(const ulonglong2*)(bp + (size_t)k * LDB);
        ulonglong2 b23 = *(const ulonglong2*)(bp + (size_t)k * LDB + 4);
#pragma unroll
        for (int i = 0; i < 8; i++) {
            unsigned long long a2 = pk2(ap[i * LDA + k]);
            FMA2(acc[i][0], a2, b01.x, acc[i][0]);
            FMA2(acc[i][1], a2, b01.y, acc[i][1]);
            FMA2(acc[i][2], a2, b23.x, acc[i][2]);
            FMA2(acc[i][3], a2, b23.y, acc[i][3]);
        }
    }

    const int m0 = bm + ty * 8;
    const int n0 = bn + tx * 8;
#pragma unroll
    for (int i = 0; i < 8; i++) {
        if (m0 + i < N_NODES) {
            unsigned long long* out =
                (unsigned long long*)(g_xw + (size_t)(m0 + i) * NCOL + n0);
            out[0] = acc[i][0];
            out[1] = acc[i][1];
            out[2] = acc[i][2];
            out[3] = acc[i][3];
        }
    }
}

// ---------------------------------------------------------------------------
// Zero the (poisoned) output
// ---------------------------------------------------------------------------
__global__ void zero_kernel(float4* __restrict__ Y4) {
    int i = blockIdx.x * blockDim.x + threadIdx.x;
    if (i < N_NODES * OUT_F / 4)
        Y4[i] = make_float4(0.f, 0.f, 0.f, 0.f);
}

// ---------------------------------------------------------------------------
// Per-edge gather from XW + vectorized atomic scatter into Y.
// 16 lanes per edge, each handling one 16B chunk of the 256B message row.
// red.global.add.v4.f32: 4 floats per reduction lane (sm_90+).
// ---------------------------------------------------------------------------
__global__ __launch_bounds__(256)
void scatter_kernel(const int* __restrict__ esrc, const int* __restrict__ edst,
                    const int* __restrict__ etyp, float* __restrict__ Y) {
    long long gid = (long long)blockIdx.x * blockDim.x + threadIdx.x;
    int e = (int)(gid >> 4);
    int l = (int)(gid & 15);
    if (e >= N_EDGES) return;

    int s = __ldg(esrc + e);
    int d = __ldg(edst + e);
    int r = __ldg(etyp + e);

    const float4 v =
        *(const float4*)(g_xw + (size_t)s * NCOL + r * OUT_F + l * 4);
    float* out = Y + (size_t)d * OUT_F + l * 4;
    asm volatile("red.global.add.v4.f32 [%0], {%1, %2, %3, %4};"
                 :: "l"(out), "f"(v.x), "f"(v.y), "f"(v.z), "f"(v.w)
                 : "memory");
}

// ---------------------------------------------------------------------------
// kernel_launch
// ---------------------------------------------------------------------------
extern "C" void kernel_launch(void* const* d_in, const int* in_sizes, int n_in,
                              void* d_out, int out_size) {
    const float* feat = (const float*)d_in[0];   // [100000, 128] f32
    const float* W    = (const float*)d_in[1];   // [8, 64, 128]  f32 (= [512,128])
    const int*   esrc = (const int*)d_in[2];     // [1638400] i32
    const int*   edst = (const int*)d_in[3];     // [1638400] i32
    const int*   etyp = (const int*)d_in[4];     // [1638400] i32
    float* Y = (float*)d_out;                    // [100000, 64] f32

    cudaFuncSetAttribute(gemm_kernel,
                         cudaFuncAttributeMaxDynamicSharedMemorySize,
                         SMEM_BYTES);

    // 1) zero output (harness poisons it)
    zero_kernel<<<(N_NODES * OUT_F / 4 + 255) / 256, 256>>>((float4*)Y);

    // 2) XW = feat @ W_flat^T
    dim3 g((N_NODES + BM - 1) / BM, NCOL / BN);
    gemm_kernel<<<g, 256, SMEM_BYTES>>>(feat, W);

    // 3) edge gather + atomic v4 scatter
    long long total = (long long)N_EDGES * 16;
    int blocks = (int)((total + 255) / 256);
    scatter_kernel<<<blocks, 256>>>(esrc, edst, etyp, Y);
}

// round 12
// speedup vs baseline: 1.9526x; 1.9526x over previous
#include <cuda_runtime.h>
#include <cuda_bf16.h>
#include <cstdint>

#define N_NODES 100000
#define N_EDGES 1638400
#define IN_F    128
#define OUT_F   64
#define N_RELS  8
#define NCOL    (N_RELS * OUT_F)   /* 512 */
#define K_TOT   384                /* 3 x 128 (hi, lo, hi) */

// Scratch (device globals — referenced ONLY from device code)
__device__ float          g_xw[(size_t)N_NODES * NCOL];          // 204.8 MB
__device__ __nv_bfloat16  g_abig[(size_t)N_NODES * K_TOT];       // 76.8 MB
__device__ __nv_bfloat16  g_bbig[(size_t)NCOL * K_TOT];          // 0.39 MB

// ---------------------------------------------------------------------------
// Baseline-ISA helpers (sm_80+; safe for the plain sm_103 ptx target)
// ---------------------------------------------------------------------------
__device__ __forceinline__ uint32_t smem_u32(const void* p) {
    uint32_t a;
    asm("{ .reg .u64 t; cvta.to.shared.u64 t, %1; cvt.u32.u64 %0, t; }"
        : "=r"(a) : "l"(p));
    return a;
}
__device__ __forceinline__ void cpasync16(uint32_t dst, const void* src, int sz) {
    asm volatile("cp.async.cg.shared.global [%0], [%1], 16, %2;"
                 :: "r"(dst), "l"(src), "r"(sz) : "memory");
}
#define CP_COMMIT() asm volatile("cp.async.commit_group;" ::: "memory")
#define CP_WAIT0()  asm volatile("cp.async.wait_group 0;" ::: "memory")
#define CP_WAIT1()  asm volatile("cp.async.wait_group 1;" ::: "memory")

__device__ __forceinline__ void ldsm4(uint32_t* r, uint32_t addr) {
    asm volatile("ldmatrix.sync.aligned.m8n8.x4.shared.b16 {%0,%1,%2,%3}, [%4];"
                 : "=r"(r[0]), "=r"(r[1]), "=r"(r[2]), "=r"(r[3]) : "r"(addr));
}
__device__ __forceinline__ void mma_bf16(float* c, const uint32_t* a,
                                         const uint32_t* b) {
    asm volatile("mma.sync.aligned.m16n8k16.row.col.f32.bf16.bf16.f32 "
                 "{%0,%1,%2,%3}, {%4,%5,%6,%7}, {%8,%9}, {%0,%1,%2,%3};"
                 : "+f"(c[0]), "+f"(c[1]), "+f"(c[2]), "+f"(c[3])
                 : "r"(a[0]), "r"(a[1]), "r"(a[2]), "r"(a[3]),
                   "r"(b[0]), "r"(b[1]));
}

// ---------------------------------------------------------------------------
// fp32 -> (hi, lo, hi) bf16 split conversion
//   A' = [Ah | Al | Ah],  B' = [Bh | Bh | Bl]
//   => A'.B'^T = Ah.Bh + Al.Bh + Ah.Bl   (drops al.bl ~ 2^-18 rel)
// ---------------------------------------------------------------------------
__global__ __launch_bounds__(256)
void conv_a_kernel(const float* __restrict__ feat) {
    int i = blockIdx.x * 256 + threadIdx.x;      // one per 4 floats
    if (i >= N_NODES * IN_F / 4) return;
    int n  = i >> 5;
    int c4 = (i & 31) * 4;
    float4 v = *(const float4*)(feat + (size_t)n * IN_F + c4);
    __nv_bfloat16 h0 = __float2bfloat16_rn(v.x), h1 = __float2bfloat16_rn(v.y);
    __nv_bfloat16 h2 = __float2bfloat16_rn(v.z), h3 = __float2bfloat16_rn(v.w);
    __nv_bfloat16 l0 = __float2bfloat16_rn(v.x - __bfloat162float(h0));
    __nv_bfloat16 l1 = __float2bfloat16_rn(v.y - __bfloat162float(h1));
    __nv_bfloat16 l2 = __float2bfloat16_rn(v.z - __bfloat162float(h2));
    __nv_bfloat16 l3 = __float2bfloat16_rn(v.w - __bfloat162float(h3));
    __nv_bfloat16* row = g_abig + (size_t)n * K_TOT;
    __nv_bfloat162* hi0 = (__nv_bfloat162*)(row + c4);
    __nv_bfloat162* lo  = (__nv_bfloat162*)(row + 128 + c4);
    __nv_bfloat162* hi1 = (__nv_bfloat162*)(row + 256 + c4);
    hi0[0] = __nv_bfloat162{h0, h1}; hi0[1] = __nv_bfloat162{h2, h3};
    lo [0] = __nv_bfloat162{l0, l1}; lo [1] = __nv_bfloat162{l2, l3};
    hi1[0] = __nv_bfloat162{h0, h1}; hi1[1] = __nv_bfloat162{h2, h3};
}

__global__ __launch_bounds__(256)
void conv_w_kernel(const float* __restrict__ W) {
    int i = blockIdx.x * 256 + threadIdx.x;
    if (i >= NCOL * IN_F / 4) return;
    int n  = i >> 5;
    int c4 = (i & 31) * 4;
    float4 v = *(const float4*)(W + (size_t)n * IN_F + c4);
    __nv_bfloat16 h0 = __float2bfloat16_rn(v.x), h1 = __float2bfloat16_rn(v.y);
    __nv_bfloat16 h2 = __float2bfloat16_rn(v.z), h3 = __float2bfloat16_rn(v.w);
    __nv_bfloat16 l0 = __float2bfloat16_rn(v.x - __bfloat162float(h0));
    __nv_bfloat16 l1 = __float2bfloat16_rn(v.y - __bfloat162float(h1));
    __nv_bfloat16 l2 = __float2bfloat16_rn(v.z - __bfloat162float(h2));
    __nv_bfloat16 l3 = __float2bfloat16_rn(v.w - __bfloat162float(h3));
    __nv_bfloat16* row = g_bbig + (size_t)n * K_TOT;
    __nv_bfloat162* hi0 = (__nv_bfloat162*)(row + c4);
    __nv_bfloat162* hi1 = (__nv_bfloat162*)(row + 128 + c4);
    __nv_bfloat162* lo  = (__nv_bfloat162*)(row + 256 + c4);
    hi0[0] = __nv_bfloat162{h0, h1}; hi0[1] = __nv_bfloat162{h2, h3};
    hi1[0] = __nv_bfloat162{h0, h1}; hi1[1] = __nv_bfloat162{h2, h3};
    lo [0] = __nv_bfloat162{l0, l1}; lo [1] = __nv_bfloat162{l2, l3};
}

// ---------------------------------------------------------------------------
// HMMA GEMM: XW[100000,512] = Abig[100000,384] @ Bbig[512,384]^T
// BM=128, BN=128, BK=64, cp.async double-buffer, ldmatrix + mma.sync bf16.
// 8 warps (2x4): each warp 64x32 via 4 m16 x 4 n8 tiles.
// ---------------------------------------------------------------------------
constexpr int GBK       = 64;
constexpr int N_STAGES  = K_TOT / GBK;           // 6
constexpr int STG       = 128 * GBK * 2;         // 16384 B per tile buffer
constexpr int SMEM_GEMM = 4 * STG;               // A0,A1,B0,B1 = 64 KB

__global__ __launch_bounds__(256)
void mma_gemm() {
    extern __shared__ char smem[];
    uint32_t sb = smem_u32(smem);
    const int tid = threadIdx.x, lane = tid & 31, wid = tid >> 5;
    const int bm = blockIdx.y * 128;
    const int bn = blockIdx.x * 128;
    const int warp_m = wid >> 2, warp_n = wid & 3;

    const __nv_bfloat16* __restrict__ Ag = g_abig;
    const __nv_bfloat16* __restrict__ Bg = g_bbig;

    // ---- stage loader: 128 rows x 64 bf16, XOR-swizzled 16B chunks ----
    const int ld_c   = tid & 7;                  // 16B chunk within row
    const int ld_r0  = tid >> 3;                 // row base (stride 32)
    auto load_stage = [&](int s) {
        uint32_t abuf = sb + (s & 1) * STG;
        uint32_t bbuf = sb + 2 * STG + (s & 1) * STG;
        const __nv_bfloat16* abase = Ag + (size_t)bm * K_TOT + s * GBK;
        const __nv_bfloat16* bbase = Bg + (size_t)bn * K_TOT + s * GBK;
#pragma unroll
        for (int it = 0; it < 4; it++) {
            int row = it * 32 + ld_r0;
            uint32_t doff = row * 128 + ((ld_c ^ (row & 7)) * 16);
            const void* asrc = abase + (size_t)row * K_TOT + ld_c * 8;
            int sz = (bm + row < N_NODES) ? 16 : 0;
            cpasync16(abuf + doff, sz ? asrc : (const void*)abase, sz);
            cpasync16(bbuf + doff, bbase + (size_t)row * K_TOT + ld_c * 8, 16);
        }
    };

    float acc[4][4][4];
#pragma unroll
    for (int i = 0; i < 4; i++)
#pragma unroll
        for (int j = 0; j < 4; j++)
#pragma unroll
            for (int k = 0; k < 4; k++) acc[i][j][k] = 0.f;

    // per-lane ldmatrix addressing bases
    const int a_row   = warp_m * 64 + (lane & 15);           // + mt*16
    const int a_choff = lane >> 4;                           // + kk*2
    const int b_row   = warp_n * 32 + (lane & 7) + ((lane & 16) >> 1); // + nb*16
    const int b_choff = (lane >> 3) & 1;                     // + kk*2

    load_stage(0); CP_COMMIT();

    for (int s = 0; s < N_STAGES; s++) {
        if (s + 1 < N_STAGES) { load_stage(s + 1); CP_COMMIT(); CP_WAIT1(); }
        else                  { CP_WAIT0(); }
        __syncthreads();

        uint32_t abuf = sb + (s & 1) * STG;
        uint32_t bbuf = sb + 2 * STG + (s & 1) * STG;
#pragma unroll
        for (int kk = 0; kk < 4; kk++) {
            uint32_t ar[4][4], br[2][4];
#pragma unroll
            for (int mt = 0; mt < 4; mt++) {
                int row = a_row + mt * 16;
                int ch  = kk * 2 + a_choff;
                ldsm4(ar[mt], abuf + row * 128 + ((ch ^ (row & 7)) * 16));
            }
#pragma unroll
            for (int nb = 0; nb < 2; nb++) {
                int row = b_row + nb * 16;
                int ch  = kk * 2 + b_choff;
                ldsm4(br[nb], bbuf + row * 128 + ((ch ^ (row & 7)) * 16));
            }
#pragma unroll
            for (int mt = 0; mt < 4; mt++)
#pragma unroll
                for (int nb = 0; nb < 2; nb++) {
                    mma_bf16(acc[mt][nb * 2 + 0], ar[mt], &br[nb][0]);
                    mma_bf16(acc[mt][nb * 2 + 1], ar[mt], &br[nb][2]);
                }
        }
        __syncthreads();
    }

    // epilogue
    const int m_base = bm + warp_m * 64 + (lane >> 2);
    const int col0   = bn + warp_n * 32 + (lane & 3) * 2;
#pragma unroll
    for (int mt = 0; mt < 4; mt++) {
        int r0 = m_base + mt * 16, r1 = r0 + 8;
#pragma unroll
        for (int j = 0; j < 4; j++) {
            int cc = col0 + j * 8;
            if (r0 < N_NODES)
                *(float2*)(g_xw + (size_t)r0 * NCOL + cc) =
                    make_float2(acc[mt][j][0], acc[mt][j][1]);
            if (r1 < N_NODES)
                *(float2*)(g_xw + (size_t)r1 * NCOL + cc) =
                    make_float2(acc[mt][j][2], acc[mt][j][3]);
        }
    }
}

// ---------------------------------------------------------------------------
// Zero the (poisoned) output
// ---------------------------------------------------------------------------
__global__ void zero_kernel(float4* __restrict__ Y4) {
    int i = blockIdx.x * blockDim.x + threadIdx.x;
    if (i < N_NODES * OUT_F / 4)
        Y4[i] = make_float4(0.f, 0.f, 0.f, 0.f);
}

// ---------------------------------------------------------------------------
// Per-edge gather from XW + vectorized atomic scatter into Y (16 lanes/edge)
// ---------------------------------------------------------------------------
__global__ __launch_bounds__(256)
void scatter_kernel(const int* __restrict__ esrc, const int* __restrict__ edst,
                    const int* __restrict__ etyp, float* __restrict__ Y) {
    long long gid = (long long)blockIdx.x * blockDim.x + threadIdx.x;
    int e = (int)(gid >> 4);
    int l = (int)(gid & 15);
    if (e >= N_EDGES) return;

    int s = __ldg(esrc + e);
    int d = __ldg(edst + e);
    int r = __ldg(etyp + e);

    const float4 v =
        *(const float4*)(g_xw + (size_t)s * NCOL + r * OUT_F + l * 4);
    float* out = Y + (size_t)d * OUT_F + l * 4;
    asm volatile("red.global.add.v4.f32 [%0], {%1, %2, %3, %4};"
                 :: "l"(out), "f"(v.x), "f"(v.y), "f"(v.z), "f"(v.w)
                 : "memory");
}

// ---------------------------------------------------------------------------
// kernel_launch
// ---------------------------------------------------------------------------
extern "C" void kernel_launch(void* const* d_in, const int* in_sizes, int n_in,
                              void* d_out, int out_size) {
    const float* feat = (const float*)d_in[0];   // [100000, 128] f32
    const float* W    = (const float*)d_in[1];   // [8, 64, 128]  f32
    const int*   esrc = (const int*)d_in[2];
    const int*   edst = (const int*)d_in[3];
    const int*   etyp = (const int*)d_in[4];
    float* Y = (float*)d_out;                    // [100000, 64] f32

    cudaFuncSetAttribute(mma_gemm,
                         cudaFuncAttributeMaxDynamicSharedMemorySize, SMEM_GEMM);

    zero_kernel<<<(N_NODES * OUT_F / 4 + 255) / 256, 256>>>((float4*)Y);
    conv_w_kernel<<<(NCOL * IN_F / 4 + 255) / 256, 256>>>(W);
    conv_a_kernel<<<(N_NODES * IN_F / 4 + 255) / 256, 256>>>(feat);

    // grid: n-blocks fastest so the 4 CTAs sharing an A tile are co-resident
    dim3 g(NCOL / 128, (N_NODES + 127) / 128);
    mma_gemm<<<g, 256, SMEM_GEMM>>>();

    long long total = (long long)N_EDGES * 16;
    scatter_kernel<<<(int)((total + 255) / 256), 256>>>(esrc, edst, etyp, Y);
}

// round 13
// speedup vs baseline: 2.2267x; 1.1404x over previous
#include <cuda_runtime.h>
#include <cuda_bf16.h>
#include <cstdint>

#define N_NODES 100000
#define N_EDGES 1638400
#define IN_F    128
#define OUT_F   64
#define N_RELS  8
#define NCOL    (N_RELS * OUT_F)   /* 512 */
#define K_TOT   384                /* 3 x 128 (hi, lo, hi) */

// Scratch (device globals — referenced ONLY from device code)
__device__ float          g_xw[(size_t)N_NODES * NCOL];          // 204.8 MB
__device__ __nv_bfloat16  g_abig[(size_t)N_NODES * K_TOT];       // 76.8 MB
__device__ __nv_bfloat16  g_bbig[(size_t)NCOL * K_TOT];          // 0.39 MB
// dst-sort scratch
__device__ int      g_cnt[N_NODES];
__device__ int      g_off[N_NODES];
__device__ int      g_cur[N_NODES];
__device__ int      g_bsum[128];
__device__ uint32_t g_perm[N_EDGES];

// ---------------------------------------------------------------------------
// Baseline-ISA helpers (sm_80+; safe for the plain sm_103 ptx target)
// ---------------------------------------------------------------------------
__device__ __forceinline__ uint32_t smem_u32(const void* p) {
    uint32_t a;
    asm("{ .reg .u64 t; cvta.to.shared.u64 t, %1; cvt.u32.u64 %0, t; }"
        : "=r"(a) : "l"(p));
    return a;
}
__device__ __forceinline__ void cpasync16(uint32_t dst, const void* src, int sz) {
    asm volatile("cp.async.cg.shared.global [%0], [%1], 16, %2;"
                 :: "r"(dst), "l"(src), "r"(sz) : "memory");
}
#define CP_COMMIT() asm volatile("cp.async.commit_group;" ::: "memory")
#define CP_WAIT0()  asm volatile("cp.async.wait_group 0;" ::: "memory")
#define CP_WAIT1()  asm volatile("cp.async.wait_group 1;" ::: "memory")

__device__ __forceinline__ void ldsm4(uint32_t* r, uint32_t addr) {
    asm volatile("ldmatrix.sync.aligned.m8n8.x4.shared.b16 {%0,%1,%2,%3}, [%4];"
                 : "=r"(r[0]), "=r"(r[1]), "=r"(r[2]), "=r"(r[3]) : "r"(addr));
}
__device__ __forceinline__ void mma_bf16(float* c, const uint32_t* a,
                                         const uint32_t* b) {
    asm volatile("mma.sync.aligned.m16n8k16.row.col.f32.bf16.bf16.f32 "
                 "{%0,%1,%2,%3}, {%4,%5,%6,%7}, {%8,%9}, {%0,%1,%2,%3};"
                 : "+f"(c[0]), "+f"(c[1]), "+f"(c[2]), "+f"(c[3])
                 : "r"(a[0]), "r"(a[1]), "r"(a[2]), "r"(a[3]),
                   "r"(b[0]), "r"(b[1]));
}

// ---------------------------------------------------------------------------
// fp32 -> (hi, lo, hi) bf16 split conversion
// ---------------------------------------------------------------------------
__global__ __launch_bounds__(256)
void conv_a_kernel(const float* __restrict__ feat) {
    int i = blockIdx.x * 256 + threadIdx.x;      // one per 4 floats
    if (i >= N_NODES * IN_F / 4) return;
    int n  = i >> 5;
    int c4 = (i & 31) * 4;
    float4 v = *(const float4*)(feat + (size_t)n * IN_F + c4);
    __nv_bfloat16 h0 = __float2bfloat16_rn(v.x), h1 = __float2bfloat16_rn(v.y);
    __nv_bfloat16 h2 = __float2bfloat16_rn(v.z), h3 = __float2bfloat16_rn(v.w);
    __nv_bfloat16 l0 = __float2bfloat16_rn(v.x - __bfloat162float(h0));
    __nv_bfloat16 l1 = __float2bfloat16_rn(v.y - __bfloat162float(h1));
    __nv_bfloat16 l2 = __float2bfloat16_rn(v.z - __bfloat162float(h2));
    __nv_bfloat16 l3 = __float2bfloat16_rn(v.w - __bfloat162float(h3));
    __nv_bfloat16* row = g_abig + (size_t)n * K_TOT;
    __nv_bfloat162* hi0 = (__nv_bfloat162*)(row + c4);
    __nv_bfloat162* lo  = (__nv_bfloat162*)(row + 128 + c4);
    __nv_bfloat162* hi1 = (__nv_bfloat162*)(row + 256 + c4);
    hi0[0] = __nv_bfloat162{h0, h1}; hi0[1] = __nv_bfloat162{h2, h3};
    lo [0] = __nv_bfloat162{l0, l1}; lo [1] = __nv_bfloat162{l2, l3};
    hi1[0] = __nv_bfloat162{h0, h1}; hi1[1] = __nv_bfloat162{h2, h3};
}

__global__ __launch_bounds__(256)
void conv_w_kernel(const float* __restrict__ W) {
    int i = blockIdx.x * 256 + threadIdx.x;
    if (i >= NCOL * IN_F / 4) return;
    int n  = i >> 5;
    int c4 = (i & 31) * 4;
    float4 v = *(const float4*)(W + (size_t)n * IN_F + c4);
    __nv_bfloat16 h0 = __float2bfloat16_rn(v.x), h1 = __float2bfloat16_rn(v.y);
    __nv_bfloat16 h2 = __float2bfloat16_rn(v.z), h3 = __float2bfloat16_rn(v.w);
    __nv_bfloat16 l0 = __float2bfloat16_rn(v.x - __bfloat162float(h0));
    __nv_bfloat16 l1 = __float2bfloat16_rn(v.y - __bfloat162float(h1));
    __nv_bfloat16 l2 = __float2bfloat16_rn(v.z - __bfloat162float(h2));
    __nv_bfloat16 l3 = __float2bfloat16_rn(v.w - __bfloat162float(h3));
    __nv_bfloat16* row = g_bbig + (size_t)n * K_TOT;
    __nv_bfloat162* hi0 = (__nv_bfloat162*)(row + c4);
    __nv_bfloat162* hi1 = (__nv_bfloat162*)(row + 128 + c4);
    __nv_bfloat162* lo  = (__nv_bfloat162*)(row + 256 + c4);
    hi0[0] = __nv_bfloat162{h0, h1}; hi0[1] = __nv_bfloat162{h2, h3};
    hi1[0] = __nv_bfloat162{h0, h1}; hi1[1] = __nv_bfloat162{h2, h3};
    lo [0] = __nv_bfloat162{l0, l1}; lo [1] = __nv_bfloat162{l2, l3};
}

// ---------------------------------------------------------------------------
// HMMA GEMM (unchanged from R12 — validated at 118.6 us)
// ---------------------------------------------------------------------------
constexpr int GBK       = 64;
constexpr int N_STAGES  = K_TOT / GBK;           // 6
constexpr int STG       = 128 * GBK * 2;         // 16384 B per tile buffer
constexpr int SMEM_GEMM = 4 * STG;               // 64 KB

__global__ __launch_bounds__(256)
void mma_gemm() {
    extern __shared__ char smem[];
    uint32_t sb = smem_u32(smem);
    const int tid = threadIdx.x, lane = tid & 31, wid = tid >> 5;
    const int bm = blockIdx.y * 128;
    const int bn = blockIdx.x * 128;
    const int warp_m = wid >> 2, warp_n = wid & 3;

    const __nv_bfloat16* __restrict__ Ag = g_abig;
    const __nv_bfloat16* __restrict__ Bg = g_bbig;

    const int ld_c   = tid & 7;
    const int ld_r0  = tid >> 3;
    auto load_stage = [&](int s) {
        uint32_t abuf = sb + (s & 1) * STG;
        uint32_t bbuf = sb + 2 * STG + (s & 1) * STG;
        const __nv_bfloat16* abase = Ag + (size_t)bm * K_TOT + s * GBK;
        const __nv_bfloat16* bbase = Bg + (size_t)bn * K_TOT + s * GBK;
#pragma unroll
        for (int it = 0; it < 4; it++) {
            int row = it * 32 + ld_r0;
            uint32_t doff = row * 128 + ((ld_c ^ (row & 7)) * 16);
            const void* asrc = abase + (size_t)row * K_TOT + ld_c * 8;
            int sz = (bm + row < N_NODES) ? 16 : 0;
            cpasync16(abuf + doff, sz ? asrc : (const void*)abase, sz);
            cpasync16(bbuf + doff, bbase + (size_t)row * K_TOT + ld_c * 8, 16);
        }
    };

    float acc[4][4][4];
#pragma unroll
    for (int i = 0; i < 4; i++)
#pragma unroll
        for (int j = 0; j < 4; j++)
#pragma unroll
            for (int k = 0; k < 4; k++) acc[i][j][k] = 0.f;

    const int a_row   = warp_m * 64 + (lane & 15);
    const int a_choff = lane >> 4;
    const int b_row   = warp_n * 32 + (lane & 7) + ((lane & 16) >> 1);
    const int b_choff = (lane >> 3) & 1;

    load_stage(0); CP_COMMIT();

    for (int s = 0; s < N_STAGES; s++) {
        if (s + 1 < N_STAGES) { load_stage(s + 1); CP_COMMIT(); CP_WAIT1(); }
        else                  { CP_WAIT0(); }
        __syncthreads();

        uint32_t abuf = sb + (s & 1) * STG;
        uint32_t bbuf = sb + 2 * STG + (s & 1) * STG;
#pragma unroll
        for (int kk = 0; kk < 4; kk++) {
            uint32_t ar[4][4], br[2][4];
#pragma unroll
            for (int mt = 0; mt < 4; mt++) {
                int row = a_row + mt * 16;
                int ch  = kk * 2 + a_choff;
                ldsm4(ar[mt], abuf + row * 128 + ((ch ^ (row & 7)) * 16));
            }
#pragma unroll
            for (int nb = 0; nb < 2; nb++) {
                int row = b_row + nb * 16;
                int ch  = kk * 2 + b_choff;
                ldsm4(br[nb], bbuf + row * 128 + ((ch ^ (row & 7)) * 16));
            }
#pragma unroll
            for (int mt = 0; mt < 4; mt++)
#pragma unroll
                for (int nb = 0; nb < 2; nb++) {
                    mma_bf16(acc[mt][nb * 2 + 0], ar[mt], &br[nb][0]);
                    mma_bf16(acc[mt][nb * 2 + 1], ar[mt], &br[nb][2]);
                }
        }
        __syncthreads();
    }

    const int m_base = bm + warp_m * 64 + (lane >> 2);
    const int col0   = bn + warp_n * 32 + (lane & 3) * 2;
#pragma unroll
    for (int mt = 0; mt < 4; mt++) {
        int r0 = m_base + mt * 16, r1 = r0 + 8;
#pragma unroll
        for (int j = 0; j < 4; j++) {
            int cc = col0 + j * 8;
            if (r0 < N_NODES)
                *(float2*)(g_xw + (size_t)r0 * NCOL + cc) =
                    make_float2(acc[mt][j][0], acc[mt][j][1]);
            if (r1 < N_NODES)
                *(float2*)(g_xw + (size_t)r1 * NCOL + cc) =
                    make_float2(acc[mt][j][2], acc[mt][j][3]);
        }
    }
}

// ---------------------------------------------------------------------------
// dst counting sort: zero counters -> histogram -> 3-pass scan -> reorder
// ---------------------------------------------------------------------------
__global__ void zcnt_kernel() {
    int i = blockIdx.x * 256 + threadIdx.x;
    if (i < N_NODES) { g_cnt[i] = 0; g_cur[i] = 0; }
}

__global__ __launch_bounds__(256)
void hist_kernel(const int* __restrict__ edst) {
    int e = blockIdx.x * 256 + threadIdx.x;
    if (e < N_EDGES) atomicAdd(&g_cnt[edst[e]], 1);
}

constexpr int SCAN_CHUNK = 1024;                       // per block
constexpr int SCAN_BLKS  = (N_NODES + SCAN_CHUNK - 1) / SCAN_CHUNK;   // 98

__global__ __launch_bounds__(256)
void scan1_kernel() {          // per-block totals
    __shared__ int sd[256];
    int b = blockIdx.x, t = threadIdx.x;
    int base = b * SCAN_CHUNK + t * 4;
    int s = 0;
#pragma unroll
    for (int j = 0; j < 4; j++) {
        int idx = base + j;
        if (idx < N_NODES) s += g_cnt[idx];
    }
    sd[t] = s; __syncthreads();
    for (int st = 128; st > 0; st >>= 1) {
        if (t < st) sd[t] += sd[t + st];
        __syncthreads();
    }
    if (t == 0) g_bsum[b] = sd[0];
}

__global__ __launch_bounds__(128)
void scan2_kernel() {          // exclusive scan of block totals (single block)
    __shared__ int sm[128];
    int t = threadIdx.x;
    int v = (t < SCAN_BLKS) ? g_bsum[t] : 0;
    sm[t] = v; __syncthreads();
    for (int st = 1; st < 128; st <<= 1) {
        int x = (t >= st) ? sm[t - st] : 0;
        __syncthreads();
        sm[t] += x;
        __syncthreads();
    }
    if (t < SCAN_BLKS) g_bsum[t] = sm[t] - v;   // exclusive
}

__global__ __launch_bounds__(256)
void scan3_kernel() {          // per-block exclusive scan + base -> g_off
    __shared__ int sd[256];
    int b = blockIdx.x, t = threadIdx.x;
    int base = b * SCAN_CHUNK + t * 4;
    int loc[4], s = 0;
#pragma unroll
    for (int j = 0; j < 4; j++) {
        int idx = base + j;
        loc[j] = (idx < N_NODES) ? g_cnt[idx] : 0;
        s += loc[j];
    }
    sd[t] = s; __syncthreads();
    for (int st = 1; st < 256; st <<= 1) {
        int x = (t >= st) ? sd[t - st] : 0;
        __syncthreads();
        sd[t] += x;
        __syncthreads();
    }
    int pre = sd[t] - s + g_bsum[b];
#pragma unroll
    for (int j = 0; j < 4; j++) {
        int idx = base + j;
        if (idx < N_NODES) { g_off[idx] = pre; pre += loc[j]; }
    }
}

__global__ __launch_bounds__(256)
void reorder_kernel(const int* __restrict__ esrc, const int* __restrict__ edst,
                    const int* __restrict__ etyp) {
    int e = blockIdx.x * 256 + threadIdx.x;
    if (e >= N_EDGES) return;
    int d = edst[e];
    int slot = g_off[d] + atomicAdd(&g_cur[d], 1);
    g_perm[slot] = (uint32_t)esrc[e] | ((uint32_t)etyp[e] << 20);
}

// ---------------------------------------------------------------------------
// Accumulate: 16 lanes per dst node; each lane owns one float4 of the 64-col
// output row. Reads sorted messages, sums in registers, single plain store.
// ---------------------------------------------------------------------------
__global__ __launch_bounds__(256)
void accum_kernel(float* __restrict__ Y) {
    int gid = blockIdx.x * 256 + threadIdx.x;
    int i = gid >> 4;
    int l = gid & 15;
    if (i >= N_NODES) return;
    int beg = __ldg(&g_off[i]);
    int end = beg + __ldg(&g_cnt[i]);
    float4 acc = make_float4(0.f, 0.f, 0.f, 0.f);
    for (int j = beg; j < end; j++) {
        uint32_t p = __ldg(&g_perm[j]);
        int s = p & 0xFFFFF;
        int r = p >> 20;
        const float4 v =
            *(const float4*)(g_xw + (size_t)s * NCOL + r * OUT_F + l * 4);
        acc.x += v.x; acc.y += v.y; acc.z += v.z; acc.w += v.w;
    }
    *(float4*)(Y + (size_t)i * OUT_F + l * 4) = acc;
}

// ---------------------------------------------------------------------------
// kernel_launch
// ---------------------------------------------------------------------------
extern "C" void kernel_launch(void* const* d_in, const int* in_sizes, int n_in,
                              void* d_out, int out_size) {
    const float* feat = (const float*)d_in[0];   // [100000, 128] f32
    const float* W    = (const float*)d_in[1];   // [8, 64, 128]  f32
    const int*   esrc = (const int*)d_in[2];
    const int*   edst = (const int*)d_in[3];
    const int*   etyp = (const int*)d_in[4];
    float* Y = (float*)d_out;                    // [100000, 64] f32

    cudaFuncSetAttribute(mma_gemm,
                         cudaFuncAttributeMaxDynamicSharedMemorySize, SMEM_GEMM);

    // --- dst counting sort (independent of GEMM inputs) ---
    zcnt_kernel<<<(N_NODES + 255) / 256, 256>>>();
    hist_kernel<<<(N_EDGES + 255) / 256, 256>>>(edst);
    scan1_kernel<<<SCAN_BLKS, 256>>>();
    scan2_kernel<<<1, 128>>>();
    scan3_kernel<<<SCAN_BLKS, 256>>>();
    reorder_kernel<<<(N_EDGES + 255) / 256, 256>>>(esrc, edst, etyp);

    // --- GEMM path ---
    conv_w_kernel<<<(NCOL * IN_F / 4 + 255) / 256, 256>>>(W);
    conv_a_kernel<<<(N_NODES * IN_F / 4 + 255) / 256, 256>>>(feat);
    dim3 g(NCOL / 128, (N_NODES + 127) / 128);
    mma_gemm<<<g, 256, SMEM_GEMM>>>();

    // --- gather + register-accumulate + plain store ---
    long long total = (long long)N_NODES * 16;
    accum_kernel<<<(int)((total + 255) / 256), 256>>>(Y);
}

// round 17
// speedup vs baseline: 2.5808x; 1.1590x over previous
#include <cuda_runtime.h>
#include <cuda_fp16.h>
#include <cstdint>

#define N_NODES 100000
#define N_EDGES 1638400
#define IN_F    128
#define OUT_F   64
#define N_RELS  8
#define NCOL    (N_RELS * OUT_F)   /* 512 */
#define K_TOT   256                /* 2 x 128 (hi, lo) fp16 split */

// Scratch (device globals — referenced ONLY from device code)
__device__ float   g_xw[(size_t)N_NODES * NCOL];          // 204.8 MB
__device__ __half  g_abig[(size_t)N_NODES * K_TOT];       // 51.2 MB
__device__ __half  g_bbig[(size_t)NCOL * K_TOT];          // 0.26 MB
// dst-sort scratch
__device__ int      g_cnt[N_NODES];
__device__ int      g_off[N_NODES];
__device__ int      g_cur[N_NODES];
__device__ int      g_bsum[128];
__device__ uint32_t g_perm[N_EDGES];

// ---------------------------------------------------------------------------
// Baseline-ISA helpers (sm_80+; safe for the plain sm_103 ptx target)
// ---------------------------------------------------------------------------
__device__ __forceinline__ uint32_t smem_u32(const void* p) {
    uint32_t a;
    asm("{ .reg .u64 t; cvta.to.shared.u64 t, %1; cvt.u32.u64 %0, t; }"
        : "=r"(a) : "l"(p));
    return a;
}
__device__ __forceinline__ void cpasync16(uint32_t dst, const void* src, int sz) {
    asm volatile("cp.async.cg.shared.global [%0], [%1], 16, %2;"
                 :: "r"(dst), "l"(src), "r"(sz) : "memory");
}
#define CP_COMMIT() asm volatile("cp.async.commit_group;" ::: "memory")
#define CP_WAIT0()  asm volatile("cp.async.wait_group 0;" ::: "memory")
#define CP_WAIT1()  asm volatile("cp.async.wait_group 1;" ::: "memory")

__device__ __forceinline__ void ldsm4(uint32_t* r, uint32_t addr) {
    asm volatile("ldmatrix.sync.aligned.m8n8.x4.shared.b16 {%0,%1,%2,%3}, [%4];"
                 : "=r"(r[0]), "=r"(r[1]), "=r"(r[2]), "=r"(r[3]) : "r"(addr));
}
__device__ __forceinline__ void mma_f16(float* c, const uint32_t* a,
                                        const uint32_t* b) {
    asm volatile("mma.sync.aligned.m16n8k16.row.col.f32.f16.f16.f32 "
                 "{%0,%1,%2,%3}, {%4,%5,%6,%7}, {%8,%9}, {%0,%1,%2,%3};"
                 : "+f"(c[0]), "+f"(c[1]), "+f"(c[2]), "+f"(c[3])
                 : "r"(a[0]), "r"(a[1]), "r"(a[2]), "r"(a[3]),
                   "r"(b[0]), "r"(b[1]));
}

// ---------------------------------------------------------------------------
// fp32 -> (hi, lo) fp16 split conversion
//   A' = [Ah | Al],  B' = [Bh | Bh]
//   => A'.B'^T = Ah.Bh + Al.Bh = a.Bh   (dropped a.Bl ~ 2^-12 rel)
// ---------------------------------------------------------------------------
__global__ __launch_bounds__(256)
void conv_a_kernel(const float* __restrict__ feat) {
    int i = blockIdx.x * 256 + threadIdx.x;      // one per 4 floats
    if (i >= N_NODES * IN_F / 4) return;
    int n  = i >> 5;
    int c4 = (i & 31) * 4;
    float4 v = *(const float4*)(feat + (size_t)n * IN_F + c4);
    __half h0 = __float2half_rn(v.x), h1 = __float2half_rn(v.y);
    __half h2 = __float2half_rn(v.z), h3 = __float2half_rn(v.w);
    __half l0 = __float2half_rn(v.x - __half2float(h0));
    __half l1 = __float2half_rn(v.y - __half2float(h1));
    __half l2 = __float2half_rn(v.z - __half2float(h2));
    __half l3 = __float2half_rn(v.w - __half2float(h3));
    __half* row = g_abig + (size_t)n * K_TOT;
    __half2* hi = (__half2*)(row + c4);
    __half2* lo = (__half2*)(row + 128 + c4);
    hi[0] = __half2{h0, h1}; hi[1] = __half2{h2, h3};
    lo[0] = __half2{l0, l1}; lo[1] = __half2{l2, l3};
}

__global__ __launch_bounds__(256)
void conv_w_kernel(const float* __restrict__ W) {
    int i = blockIdx.x * 256 + threadIdx.x;
    if (i >= NCOL * IN_F / 4) return;
    int n  = i >> 5;
    int c4 = (i & 31) * 4;
    float4 v = *(const float4*)(W + (size_t)n * IN_F + c4);
    __half h0 = __float2half_rn(v.x), h1 = __float2half_rn(v.y);
    __half h2 = __float2half_rn(v.z), h3 = __float2half_rn(v.w);
    __half* row = g_bbig + (size_t)n * K_TOT;
    __half2* hi0 = (__half2*)(row + c4);
    __half2* hi1 = (__half2*)(row + 128 + c4);
    hi0[0] = __half2{h0, h1}; hi0[1] = __half2{h2, h3};
    hi1[0] = __half2{h0, h1}; hi1[1] = __half2{h2, h3};
}

// ---------------------------------------------------------------------------
// HMMA GEMM: XW[100000,512] = Abig[100000,256] @ Bbig[512,256]^T (fp16)
// BM=128, BN=128, BK=64, cp.async double-buffer, ldmatrix + mma.sync.
// ---------------------------------------------------------------------------
constexpr int GBK       = 64;
constexpr int N_STAGES  = K_TOT / GBK;           // 4
constexpr int STG       = 128 * GBK * 2;         // 16384 B per tile buffer
constexpr int SMEM_GEMM = 4 * STG;               // 64 KB

__global__ __launch_bounds__(256)
void mma_gemm() {
    extern __shared__ char smem[];
    uint32_t sb = smem_u32(smem);
    const int tid = threadIdx.x, lane = tid & 31, wid = tid >> 5;
    const int bm = blockIdx.y * 128;
    const int bn = blockIdx.x * 128;
    const int warp_m = wid >> 2, warp_n = wid & 3;

    const __half* __restrict__ Ag = g_abig;
    const __half* __restrict__ Bg = g_bbig;

    const int ld_c   = tid & 7;
    const int ld_r0  = tid >> 3;
    auto load_stage = [&](int s) {
        uint32_t abuf = sb + (s & 1) * STG;
        uint32_t bbuf = sb + 2 * STG + (s & 1) * STG;
        const __half* abase = Ag + (size_t)bm * K_TOT + s * GBK;
        const __half* bbase = Bg + (size_t)bn * K_TOT + s * GBK;
#pragma unroll
        for (int it = 0; it < 4; it++) {
            int row = it * 32 + ld_r0;
            uint32_t doff = row * 128 + ((ld_c ^ (row & 7)) * 16);
            const void* asrc = abase + (size_t)row * K_TOT + ld_c * 8;
            int sz = (bm + row < N_NODES) ? 16 : 0;
            cpasync16(abuf + doff, sz ? asrc : (const void*)abase, sz);
            cpasync16(bbuf + doff, bbase + (size_t)row * K_TOT + ld_c * 8, 16);
        }
    };

    float acc[4][4][4];
#pragma unroll
    for (int i = 0; i < 4; i++)
#pragma unroll
        for (int j = 0; j < 4; j++)
#pragma unroll
            for (int k = 0; k < 4; k++) acc[i][j][k] = 0.f;

    const int a_row   = warp_m * 64 + (lane & 15);
    const int a_choff = lane >> 4;
    const int b_row   = warp_n * 32 + (lane & 7) + ((lane & 16) >> 1);
    const int b_choff = (lane >> 3) & 1;

    load_stage(0); CP_COMMIT();

    for (int s = 0; s < N_STAGES; s++) {
        if (s + 1 < N_STAGES) { load_stage(s + 1); CP_COMMIT(); CP_WAIT1(); }
        else                  { CP_WAIT0(); }
        __syncthreads();

        uint32_t abuf = sb + (s & 1) * STG;
        uint32_t bbuf = sb + 2 * STG + (s & 1) * STG;
#pragma unroll
        for (int kk = 0; kk < 4; kk++) {
            uint32_t ar[4][4], br[2][4];
#pragma unroll
            for (int mt = 0; mt < 4; mt++) {
                int row = a_row + mt * 16;
                int ch  = kk * 2 + a_choff;
                ldsm4(ar[mt], abuf + row * 128 + ((ch ^ (row & 7)) * 16));
            }
#pragma unroll
            for (int nb = 0; nb < 2; nb++) {
                int row = b_row + nb * 16;
                int ch  = kk * 2 + b_choff;
                ldsm4(br[nb], bbuf + row * 128 + ((ch ^ (row & 7)) * 16));
            }
#pragma unroll
            for (int mt = 0; mt < 4; mt++)
#pragma unroll
                for (int nb = 0; nb < 2; nb++) {
                    mma_f16(acc[mt][nb * 2 + 0], ar[mt], &br[nb][0]);
                    mma_f16(acc[mt][nb * 2 + 1], ar[mt], &br[nb][2]);
                }
        }
        __syncthreads();
    }

    const int m_base = bm + warp_m * 64 + (lane >> 2);
    const int col0   = bn + warp_n * 32 + (lane & 3) * 2;
#pragma unroll
    for (int mt = 0; mt < 4; mt++) {
        int r0 = m_base + mt * 16, r1 = r0 + 8;
#pragma unroll
        for (int j = 0; j < 4; j++) {
            int cc = col0 + j * 8;
            if (r0 < N_NODES)
                *(float2*)(g_xw + (size_t)r0 * NCOL + cc) =
                    make_float2(acc[mt][j][0], acc[mt][j][1]);
            if (r1 < N_NODES)
                *(float2*)(g_xw + (size_t)r1 * NCOL + cc) =
                    make_float2(acc[mt][j][2], acc[mt][j][3]);
        }
    }
}

// ---------------------------------------------------------------------------
// dst counting sort: zero counters -> histogram -> 3-pass scan -> reorder
// ---------------------------------------------------------------------------
__global__ void zcnt_kernel() {
    int i = blockIdx.x * 256 + threadIdx.x;
    if (i < N_NODES) { g_cnt[i] = 0; g_cur[i] = 0; }
}

__global__ __launch_bounds__(256)
void hist_kernel(const int* __restrict__ edst) {
    int e = blockIdx.x * 256 + threadIdx.x;
    if (e < N_EDGES) atomicAdd(&g_cnt[edst[e]], 1);
}

constexpr int SCAN_CHUNK = 1024;                       // per block
constexpr int SCAN_BLKS  = (N_NODES + SCAN_CHUNK - 1) / SCAN_CHUNK;   // 98

__global__ __launch_bounds__(256)
void scan1_kernel() {          // per-block totals
    __shared__ int sd[256];
    int b = blockIdx.x, t = threadIdx.x;
    int base = b * SCAN_CHUNK + t * 4;
    int s = 0;
#pragma unroll
    for (int j = 0; j < 4; j++) {
        int idx = base + j;
        if (idx < N_NODES) s += g_cnt[idx];
    }
    sd[t] = s; __syncthreads();
    for (int st = 128; st > 0; st >>= 1) {
        if (t < st) sd[t] += sd[t + st];
        __syncthreads();
    }
    if (t == 0) g_bsum[b] = sd[0];
}

__global__ __launch_bounds__(128)
void scan2_kernel() {          // exclusive scan of block totals (single block)
    __shared__ int sm[128];
    int t = threadIdx.x;
    int v = (t < SCAN_BLKS) ? g_bsum[t] : 0;
    sm[t] = v; __syncthreads();
    for (int st = 1; st < 128; st <<= 1) {
        int x = (t >= st) ? sm[t - st] : 0;
        __syncthreads();
        sm[t] += x;
        __syncthreads();
    }
    if (t < SCAN_BLKS) g_bsum[t] = sm[t] - v;   // exclusive
}

__global__ __launch_bounds__(256)
void scan3_kernel() {          // per-block exclusive scan + base -> g_off
    __shared__ int sd[256];
    int b = blockIdx.x, t = threadIdx.x;
    int base = b * SCAN_CHUNK + t * 4;
    int loc[4], s = 0;
#pragma unroll
    for (int j = 0; j < 4; j++) {
        int idx = base + j;
        loc[j] = (idx < N_NODES) ? g_cnt[idx] : 0;
        s += loc[j];
    }
    sd[t] = s; __syncthreads();
    for (int st = 1; st < 256; st <<= 1) {
        int x = (t >= st) ? sd[t - st] : 0;
        __syncthreads();
        sd[t] += x;
        __syncthreads();
    }
    int pre = sd[t] - s + g_bsum[b];
#pragma unroll
    for (int j = 0; j < 4; j++) {
        int idx = base + j;
        if (idx < N_NODES) { g_off[idx] = pre; pre += loc[j]; }
    }
}

__global__ __launch_bounds__(256)
void reorder_kernel(const int* __restrict__ esrc, const int* __restrict__ edst,
                    const int* __restrict__ etyp) {
    int e = blockIdx.x * 256 + threadIdx.x;
    if (e >= N_EDGES) return;
    int d = edst[e];
    int slot = g_off[d] + atomicAdd(&g_cur[d], 1);
    g_perm[slot] = (uint32_t)esrc[e] | ((uint32_t)etyp[e] << 20);
}

// ---------------------------------------------------------------------------
// Accumulate: 16 lanes per dst node; each lane owns one float4 of the 64-col
// output row. Reads sorted messages, sums in registers, single plain store.
// ---------------------------------------------------------------------------
__global__ __launch_bounds__(256)
void accum_kernel(float* __restrict__ Y) {
    int gid = blockIdx.x * 256 + threadIdx.x;
    int i = gid >> 4;
    int l = gid & 15;
    if (i >= N_NODES) return;
    int beg = __ldg(&g_off[i]);
    int end = beg + __ldg(&g_cnt[i]);
    float4 acc = make_float4(0.f, 0.f, 0.f, 0.f);
    for (int j = beg; j < end; j++) {
        uint32_t p = __ldg(&g_perm[j]);
        int s = p & 0xFFFFF;
        int r = p >> 20;
        const float4 v =
            *(const float4*)(g_xw + (size_t)s * NCOL + r * OUT_F + l * 4);
        acc.x += v.x; acc.y += v.y; acc.z += v.z; acc.w += v.w;
    }
    *(float4*)(Y + (size_t)i * OUT_F + l * 4) = acc;
}

// ---------------------------------------------------------------------------
// kernel_launch
// ---------------------------------------------------------------------------
extern "C" void kernel_launch(void* const* d_in, const int* in_sizes, int n_in,
                              void* d_out, int out_size) {
    const float* feat = (const float*)d_in[0];   // [100000, 128] f32
    const float* W    = (const float*)d_in[1];   // [8, 64, 128]  f32
    const int*   esrc = (const int*)d_in[2];
    const int*   edst = (const int*)d_in[3];
    const int*   etyp = (const int*)d_in[4];
    float* Y = (float*)d_out;                    // [100000, 64] f32

    cudaFuncSetAttribute(mma_gemm,
                         cudaFuncAttributeMaxDynamicSharedMemorySize, SMEM_GEMM);

    // --- dst counting sort (independent of GEMM inputs) ---
    zcnt_kernel<<<(N_NODES + 255) / 256, 256>>>();
    hist_kernel<<<(N_EDGES + 255) / 256, 256>>>(edst);
    scan1_kernel<<<SCAN_BLKS, 256>>>();
    scan2_kernel<<<1, 128>>>();
    scan3_kernel<<<SCAN_BLKS, 256>>>();
    reorder_kernel<<<(N_EDGES + 255) / 256, 256>>>(esrc, edst, etyp);

    // --- GEMM path ---
    conv_w_kernel<<<(NCOL * IN_F / 4 + 255) / 256, 256>>>(W);
    conv_a_kernel<<<(N_NODES * IN_F / 4 + 255) / 256, 256>>>(feat);
    dim3 g(NCOL / 128, (N_NODES + 127) / 128);
    mma_gemm<<<g, 256, SMEM_GEMM>>>();

    // --- gather + register-accumulate + plain store ---
    long long total = (long long)N_NODES * 16;
    accum_kernel<<<(int)((total + 255) / 256), 256>>>(Y);
}